// round 16
// baseline (speedup 1.0000x reference)
#include <cuda_runtime.h>
#include <cuda_fp16.h>
#include <math.h>
#include <stdint.h>

// ---------------- problem constants ----------------
#define BB 4
#define LL 2048
#define DM 1024
#define DIP 4368          // 2*D_INNER + 2*D_STATE + NHEADS
#define DINNER 2048
#define CONVD 2304        // D_INNER + 2*D_STATE
#define NH 16
#define HP 128            // head dim
#define NS 128            // state dim
#define CS 256            // chunk size
#define NC 8              // chunks per sequence

// ---------------- scratch (device globals; no allocation) ----------------
__device__ __half g_zx_h[(size_t)BB * LL * DIP];      // in-proj output (fp16)
__device__ __half g_xc_h[(size_t)BB * LL * CONVD];    // conv+silu output (fp16)
__device__ float g_dt[(size_t)BB * LL * NH];          // softplus(dt)
__device__ float g_Acs[(size_t)BB * NH * NC * CS];    // per-chunk inclusive cumsum of dA
__device__ float g_CBT[(size_t)BB * NC * CS * CS];    // C @ B^T per (b,chunk)
__device__ __half g_states_h[(size_t)BB * NC * NH * HP * NS];
__device__ __half g_prev_h[(size_t)BB * NC * NH * HP * NS];
__device__ __half g_y_h[(size_t)BB * LL * DINNER];    // pre-out-proj activations (fp16)
__device__ __half g_u_h[(size_t)BB * LL * DM];        // fp16 u
__device__ __half g_Win_h[(size_t)DIP * DM];          // fp16 W_in
__device__ __half g_Wout_h[(size_t)DM * DINNER];      // fp16 W_out
__device__ __half g_yg_h[(size_t)BB * LL * DINNER];   // fp16 gated+normed y

// ---------------- helpers ----------------
__device__ __forceinline__ void mma_fp16(float c[4], const uint32_t a[4], const uint32_t b[2]) {
    asm volatile(
        "mma.sync.aligned.m16n8k16.row.col.f32.f16.f16.f32 "
        "{%0,%1,%2,%3}, {%4,%5,%6,%7}, {%8,%9}, {%0,%1,%2,%3};"
        : "+f"(c[0]), "+f"(c[1]), "+f"(c[2]), "+f"(c[3])
        : "r"(a[0]), "r"(a[1]), "r"(a[2]), "r"(a[3]), "r"(b[0]), "r"(b[1]));
}

__device__ __forceinline__ void ldsm4(uint32_t& r0, uint32_t& r1, uint32_t& r2, uint32_t& r3,
                                      uint32_t addr) {
    asm volatile("ldmatrix.sync.aligned.m8n8.x4.shared.b16 {%0,%1,%2,%3}, [%4];"
                 : "=r"(r0), "=r"(r1), "=r"(r2), "=r"(r3) : "r"(addr));
}

__device__ __forceinline__ void ldsm4t(uint32_t& r0, uint32_t& r1, uint32_t& r2, uint32_t& r3,
                                       uint32_t addr) {
    asm volatile("ldmatrix.sync.aligned.m8n8.x4.trans.shared.b16 {%0,%1,%2,%3}, [%4];"
                 : "=r"(r0), "=r"(r1), "=r"(r2), "=r"(r3) : "r"(addr));
}

__device__ __forceinline__ void cp16(uint32_t dst, const void* src, bool ok) {
    int sz = ok ? 16 : 0;
    asm volatile("cp.async.ca.shared.global [%0], [%1], 16, %2;\n"
                 :: "r"(dst), "l"(src), "r"(sz));
}
#define CP_COMMIT() asm volatile("cp.async.commit_group;\n")
#define CP_WAIT1()  asm volatile("cp.async.wait_group 1;\n" ::: "memory")

// ---------------- elementwise fp32 -> fp16 ----------------
__global__ void round_fp16(const float* __restrict__ s, __half* __restrict__ d, int n)
{
    int i = (blockIdx.x * 256 + threadIdx.x) * 4;
    if (i >= n) return;
    float4 v = *(const float4*)(s + i);
    *(__half2*)(d + i)     = __floats2half2_rn(v.x, v.y);
    *(__half2*)(d + i + 2) = __floats2half2_rn(v.z, v.w);
}

// ---------------- fp16 NT GEMM: 256 threads, 8 warps, 256x128 CTA tile ----------------
// Dual-chunk fragment prefetch: all ldmatrix for both k16 chunks issued before MMAs.
#define GSTG 3
#define A_STG_B (256 * 80)
#define B_STG_B (128 * 80)
#define GB_OFF (GSTG * A_STG_B)
__global__ __launch_bounds__(256, 1) void gemm_fp16_nt(
    const __half* __restrict__ A, int lda, long long sA,
    const __half* __restrict__ B, int ldb, long long sB,
    void* __restrict__ C, int ldc, long long sC,
    int N, int K, int outHalf)
{
    extern __shared__ char smraw[];
    const __half* Ab = A + (size_t)blockIdx.z * sA;
    const __half* Bb = B + (size_t)blockIdx.z * sB;
    const int m0 = blockIdx.y * 256, n0 = blockIdx.x * 128;
    const int t = threadIdx.x;
    const int lane = t & 31, w = t >> 5;
    const int wm = (w >> 1) * 64, wn = (w & 1) * 64;

    const bool bldr = (t < 128);
    const bool bok = bldr && ((n0 + t) < N);
    const __half* aS = Ab + (size_t)(m0 + t) * lda;
    const __half* bS = Bb + (size_t)(bok ? n0 + t : 0) * ldb;
    const uint32_t smBase = (uint32_t)__cvta_generic_to_shared(smraw);
    const uint32_t dA = smBase + t * 80;
    const uint32_t dB = smBase + GB_OFF + t * 80;

    const uint32_t aFragOff = (uint32_t)((wm + (lane & 15)) * 80 + (lane >> 4) * 16);
    const uint32_t bFragOff = (uint32_t)((wn + ((lane >> 4) << 3) + (lane & 7)) * 80
                                         + ((lane >> 3) & 1) * 16);

    float acc[4][8][4];
    #pragma unroll
    for (int i = 0; i < 4; i++)
        #pragma unroll
        for (int j = 0; j < 8; j++)
            #pragma unroll
            for (int q = 0; q < 4; q++) acc[i][j][q] = 0.f;

    const int nIter = K >> 5;
    #pragma unroll
    for (int s = 0; s < GSTG - 1; s++) {
        const uint32_t offA = s * A_STG_B;
        const uint32_t offB = s * B_STG_B;
        const int k0 = s << 5;
        cp16(dA + offA,      aS + k0,      true);
        cp16(dA + offA + 16, aS + k0 + 8,  true);
        cp16(dA + offA + 32, aS + k0 + 16, true);
        cp16(dA + offA + 48, aS + k0 + 24, true);
        if (bldr) {
            cp16(dB + offB,      bS + k0,      bok);
            cp16(dB + offB + 16, bS + k0 + 8,  bok);
            cp16(dB + offB + 32, bS + k0 + 16, bok);
            cp16(dB + offB + 48, bS + k0 + 24, bok);
        }
        CP_COMMIT();
    }

    for (int it = 0; it < nIter; it++) {
        CP_WAIT1();
        __syncthreads();
        const int pf = it + GSTG - 1;
        if (pf < nIter) {
            const uint32_t offA = (pf % GSTG) * A_STG_B;
            const uint32_t offB = (pf % GSTG) * B_STG_B;
            const int k0 = pf << 5;
            cp16(dA + offA,      aS + k0,      true);
            cp16(dA + offA + 16, aS + k0 + 8,  true);
            cp16(dA + offA + 32, aS + k0 + 16, true);
            cp16(dA + offA + 48, aS + k0 + 24, true);
            if (bldr) {
                cp16(dB + offB,      bS + k0,      bok);
                cp16(dB + offB + 16, bS + k0 + 8,  bok);
                cp16(dB + offB + 32, bS + k0 + 16, bok);
                cp16(dB + offB + 48, bS + k0 + 24, bok);
            }
        }
        CP_COMMIT();

        const uint32_t aOct = smBase + (it % GSTG) * A_STG_B + aFragOff;
        const uint32_t bOct = smBase + GB_OFF + (it % GSTG) * B_STG_B + bFragOff;
        uint32_t afr[2][4][4], bfr[2][8][2];
        #pragma unroll
        for (int ck = 0; ck < 2; ck++) {
            #pragma unroll
            for (int mi = 0; mi < 4; mi++)
                ldsm4(afr[ck][mi][0], afr[ck][mi][1], afr[ck][mi][2], afr[ck][mi][3],
                      aOct + ck * 32 + mi * (16 * 80));
            #pragma unroll
            for (int j = 0; j < 4; j++)
                ldsm4(bfr[ck][2 * j][0], bfr[ck][2 * j][1],
                      bfr[ck][2 * j + 1][0], bfr[ck][2 * j + 1][1],
                      bOct + ck * 32 + j * (16 * 80));
        }
        #pragma unroll
        for (int ck = 0; ck < 2; ck++)
            #pragma unroll
            for (int mi = 0; mi < 4; mi++)
                #pragma unroll
                for (int ni = 0; ni < 8; ni++)
                    mma_fp16(acc[mi][ni], afr[ck][mi], bfr[ck][ni]);
    }

    const int g = lane >> 2, tt = lane & 3;
    if (outHalf) {
        __half* Cb = (__half*)C + (size_t)blockIdx.z * sC;
        #pragma unroll
        for (int mi = 0; mi < 4; mi++)
            #pragma unroll
            for (int ni = 0; ni < 8; ni++) {
                int row = m0 + wm + mi * 16 + g;
                int col = n0 + wn + ni * 8 + 2 * tt;
                if (col < N) {
                    *(__half2*)(Cb + (size_t)row * ldc + col) =
                        __floats2half2_rn(acc[mi][ni][0], acc[mi][ni][1]);
                    *(__half2*)(Cb + (size_t)(row + 8) * ldc + col) =
                        __floats2half2_rn(acc[mi][ni][2], acc[mi][ni][3]);
                }
            }
    } else {
        float* Cb = (float*)C + (size_t)blockIdx.z * sC;
        #pragma unroll
        for (int mi = 0; mi < 4; mi++)
            #pragma unroll
            for (int ni = 0; ni < 8; ni++) {
                int row = m0 + wm + mi * 16 + g;
                int col = n0 + wn + ni * 8 + 2 * tt;
                if (col < N) {
                    *(float2*)(Cb + (size_t)row * ldc + col) =
                        make_float2(acc[mi][ni][0], acc[mi][ni][1]);
                    *(float2*)(Cb + (size_t)(row + 8) * ldc + col) =
                        make_float2(acc[mi][ni][2], acc[mi][ni][3]);
                }
            }
    }
}

// ---------------- depthwise conv (K=4) + SiLU + dt softplus ----------------
__global__ void conv_silu_dt(const float* __restrict__ conv_w,
                             const float* __restrict__ conv_b,
                             const float* __restrict__ dt_bias)
{
    const int bl = blockIdx.y;
    const int l = bl & (LL - 1);
    const int c = blockIdx.x * 256 + threadIdx.x;
    float acc = conv_b[c];
    #pragma unroll
    for (int k = 0; k < 4; k++) {
        int ls = l + k - 3;
        if (ls >= 0)
            acc += __half2float(g_zx_h[(size_t)(bl + k - 3) * DIP + DINNER + c])
                   * conv_w[c * 4 + k];
    }
    acc = acc / (1.f + __expf(-acc));
    g_xc_h[(size_t)bl * CONVD + c] = __float2half(acc);

    if (blockIdx.x == 0 && threadIdx.x < NH) {
        float x = __half2float(g_zx_h[(size_t)bl * DIP + DINNER + CONVD + threadIdx.x])
                  + dt_bias[threadIdx.x];
        float sp = (x > 20.f) ? x : log1pf(__expf(x));
        g_dt[(size_t)bl * NH + threadIdx.x] = sp;
    }
}

// ---------------- per-chunk inclusive cumsum of dA = dt * A ----------------
__global__ void chunk_cumsum(const float* __restrict__ A_log)
{
    const int idx = blockIdx.x;
    const int c = idx % NC;
    const int h = (idx / NC) % NH;
    const int b = idx / (NC * NH);
    const int s = threadIdx.x;
    __shared__ float sh[CS];
    float Ah = -__expf(A_log[h]);
    sh[s] = g_dt[((size_t)b * LL + c * CS + s) * NH + h] * Ah;
    __syncthreads();
    for (int off = 1; off < CS; off <<= 1) {
        float u = (s >= off) ? sh[s - off] : 0.f;
        __syncthreads();
        sh[s] += u;
        __syncthreads();
    }
    g_Acs[(size_t)idx * CS + s] = sh[s];
}

// ---------------- states (fp16 MMA, 256 threads, BK=32, trans ldmatrix) ----------------
#define KM_STRIDE 272   // bytes per k-row (128 halves + 8 pad)
__global__ __launch_bounds__(256, 2) void states_fp16()
{
    const int z = blockIdx.x;
    const int h = z % NH;
    const int bc = z / NH;
    const int c = bc % NC;
    const int b = bc / NC;
    __shared__ __half Xs[32][136];
    __shared__ __half Bs[32][136];
    __shared__ float ws[CS];
    const int t = threadIdx.x;
    {
        const float* acs = g_Acs + ((size_t)(b * NH + h) * NC + c) * CS;
        float last = acs[CS - 1];
        float dtv = g_dt[((size_t)b * LL + c * CS + t) * NH + h];
        ws[t] = dtv * __expf(last - acs[t]);
    }
    __syncthreads();
    const int lane = t & 31, w = t >> 5;
    const int wm = (w & 1) * 64, wn = (w >> 1) * 32;
    const int lr = t >> 3, lc = (t & 7) * 16;   // loader: 32 rows x 128 halves
    const uint32_t smX = (uint32_t)__cvta_generic_to_shared(&Xs[0][0]);
    const uint32_t smB = (uint32_t)__cvta_generic_to_shared(&Bs[0][0]);
    const uint32_t aRowOff = (uint32_t)(((lane & 7) + ((lane >> 4) << 3)) * KM_STRIDE
                                        + ((lane >> 3) & 1) * 16);
    const uint32_t bRowOff = (uint32_t)(((lane & 7) + ((lane >> 3) & 1) * 8) * KM_STRIDE
                                        + ((lane >> 4) << 4));

    float acc[4][4][4];
    #pragma unroll
    for (int i = 0; i < 4; i++)
        #pragma unroll
        for (int j = 0; j < 4; j++)
            #pragma unroll
            for (int q = 0; q < 4; q++) acc[i][j][q] = 0.f;

    const __half* xbase = g_xc_h + ((size_t)b * LL + c * CS) * CONVD + h * HP;
    const __half* bbase = g_xc_h + ((size_t)b * LL + c * CS) * CONVD + DINNER;

    for (int k0 = 0; k0 < CS; k0 += 32) {
        const __half2 wsv2 = __float2half2_rn(ws[k0 + lr]);
        const __half* xr = xbase + (size_t)(k0 + lr) * CONVD + lc;
        const __half* br = bbase + (size_t)(k0 + lr) * CONVD + lc;
        #pragma unroll
        for (int q = 0; q < 2; q++) {
            uint4 xv = *(const uint4*)(xr + q * 8);
            __half2* xp = (__half2*)&xv;
            #pragma unroll
            for (int e = 0; e < 4; e++) xp[e] = __hmul2(xp[e], wsv2);
            *(uint4*)&Xs[lr][lc + q * 8] = xv;
            *(uint4*)&Bs[lr][lc + q * 8] = *(const uint4*)(br + q * 8);
        }
        __syncthreads();
        #pragma unroll
        for (int ck = 0; ck < 2; ck++) {
            uint32_t afr[4][4], bfr[4][2];
            const uint32_t cOff = ck * 16 * KM_STRIDE;
            #pragma unroll
            for (int mi = 0; mi < 4; mi++)
                ldsm4t(afr[mi][0], afr[mi][1], afr[mi][2], afr[mi][3],
                       smX + cOff + aRowOff + (wm + mi * 16) * 2);
            #pragma unroll
            for (int np = 0; np < 2; np++)
                ldsm4t(bfr[2 * np][0], bfr[2 * np][1], bfr[2 * np + 1][0], bfr[2 * np + 1][1],
                       smB + cOff + bRowOff + (wn + np * 16) * 2);
            #pragma unroll
            for (int mi = 0; mi < 4; mi++)
                #pragma unroll
                for (int ni = 0; ni < 4; ni++)
                    mma_fp16(acc[mi][ni], afr[mi], bfr[ni]);
        }
        __syncthreads();
    }

    __half* sout = g_states_h + (size_t)z * HP * NS;
    const int g = lane >> 2, tt = lane & 3;
    #pragma unroll
    for (int mi = 0; mi < 4; mi++)
        #pragma unroll
        for (int ni = 0; ni < 4; ni++) {
            int row = wm + mi * 16 + g;
            int col = wn + ni * 8 + 2 * tt;
            *(__half2*)(sout + (size_t)row * NS + col) =
                __floats2half2_rn(acc[mi][ni][0], acc[mi][ni][1]);
            *(__half2*)(sout + (size_t)(row + 8) * NS + col) =
                __floats2half2_rn(acc[mi][ni][2], acc[mi][ni][3]);
        }
}

// ---------------- sequential scan over chunks (half2, element-parallel) ----------------
__global__ void chunk_scan()
{
    const int bh = blockIdx.x;
    const int b = bh / NH, h = bh % NH;
    __shared__ float dec[NC];
    if (threadIdx.x < NC)
        dec[threadIdx.x] = __expf(g_Acs[((size_t)(b * NH + h) * NC + threadIdx.x) * CS + CS - 1]);
    __syncthreads();
    const int idx = (blockIdx.y * 256 + threadIdx.x) * 2;
    float2 carry = make_float2(0.f, 0.f);
    #pragma unroll
    for (int c = 0; c < NC; c++) {
        size_t base = ((size_t)((b * NC + c) * NH + h)) * HP * NS + idx;
        *(__half2*)(g_prev_h + base) = __floats2half2_rn(carry.x, carry.y);
        float2 s = __half22float2(*(const __half2*)(g_states_h + base));
        carry.x = carry.x * dec[c] + s.x;
        carry.y = carry.y * dec[c] + s.y;
    }
}

// ---------------- Y (fp16 MMA, 256 threads, BK=32) ----------------
#define RM2_STRIDE 80   // bytes per row (32 halves + 8 pad)
__global__ __launch_bounds__(256, 2) void y_fp16(const float* __restrict__ Dp)
{
    const int z = blockIdx.y;
    const int h = z % NH;
    const int bc = z / NH;
    const int c = bc % NC;
    const int b = bc / NC;
    const int m0 = blockIdx.x * 128;

    __shared__ float sAcs[CS], sdt[CS];
    __shared__ float sh_e[32];
    __shared__ __half As[128][40];
    __shared__ __half Bt[32][136];
    __shared__ __half B2[128][40];
    const int t = threadIdx.x;
    {
        const float* acs = g_Acs + ((size_t)(b * NH + h) * NC + c) * CS;
        sAcs[t] = acs[t];
        sdt[t] = g_dt[((size_t)b * LL + c * CS + t) * NH + h];
    }
    __syncthreads();

    const int lane = t & 31, w = t >> 5;
    const int wm = (w & 1) * 64, wn = (w >> 1) * 32;
    const int arow = t >> 1, ac16 = (t & 1) * 16;
    const int l_loc = m0 + arow;
    const float acs_l = sAcs[l_loc];
    const __half2 eAl2 = __float2half2_rn(__expf(acs_l));
    const int xr32 = t >> 3, xc16 = (t & 7) * 16;

    const uint32_t smA  = (uint32_t)__cvta_generic_to_shared(&As[0][0]);
    const uint32_t smBt = (uint32_t)__cvta_generic_to_shared(&Bt[0][0]);
    const uint32_t smB2 = (uint32_t)__cvta_generic_to_shared(&B2[0][0]);
    const uint32_t aFrag  = (uint32_t)((wm + (lane & 15)) * RM2_STRIDE + (lane >> 4) * 16);
    const uint32_t btFrag = (uint32_t)(((lane & 7) + ((lane >> 3) & 1) * 8) * KM_STRIDE
                                       + ((lane >> 4) << 4));
    const uint32_t b2Frag = (uint32_t)((wn + ((lane >> 4) << 3) + (lane & 7)) * RM2_STRIDE
                                       + ((lane >> 3) & 1) * 16);

    float acc[4][4][4];
    #pragma unroll
    for (int i = 0; i < 4; i++)
        #pragma unroll
        for (int j = 0; j < 4; j++)
            #pragma unroll
            for (int q = 0; q < 4; q++) acc[i][j][q] = 0.f;

    const float* cbt_l = g_CBT + (size_t)bc * CS * CS + (size_t)l_loc * CS;
    const __half* xrow = g_xc_h + ((size_t)b * LL + c * CS) * CONVD + h * HP;

    // ---- phase 1: intra-chunk, K = m0+128, BK=32 (factorized decay exp) ----
    const int K1 = m0 + 128;
    for (int k0 = 0; k0 < K1; k0 += 32) {
        if (t < 32)
            sh_e[t] = __expf(sAcs[k0 + 31] - sAcs[k0 + t]) * sdt[k0 + t];
        __syncthreads();
        const float e_row = (l_loc >= k0) ? __expf(acs_l - sAcs[k0 + 31]) : 0.f;
        #pragma unroll
        for (int j = 0; j < 16; j += 2) {
            int s = k0 + ac16 + j;
            float v0 = (s     <= l_loc) ? cbt_l[s]     * e_row * sh_e[ac16 + j]     : 0.f;
            float v1 = (s + 1 <= l_loc) ? cbt_l[s + 1] * e_row * sh_e[ac16 + j + 1] : 0.f;
            *(__half2*)&As[arow][ac16 + j] = __floats2half2_rn(v0, v1);
        }
        const __half* xr = xrow + (size_t)(k0 + xr32) * CONVD + xc16;
        *(uint4*)&Bt[xr32][xc16]     = *(const uint4*)(xr);
        *(uint4*)&Bt[xr32][xc16 + 8] = *(const uint4*)(xr + 8);
        __syncthreads();
        #pragma unroll
        for (int ck = 0; ck < 2; ck++) {
            uint32_t afr[4][4], bfr[4][2];
            #pragma unroll
            for (int mi = 0; mi < 4; mi++)
                ldsm4(afr[mi][0], afr[mi][1], afr[mi][2], afr[mi][3],
                      smA + aFrag + ck * 32 + mi * (16 * RM2_STRIDE));
            #pragma unroll
            for (int np = 0; np < 2; np++)
                ldsm4t(bfr[2 * np][0], bfr[2 * np][1], bfr[2 * np + 1][0], bfr[2 * np + 1][1],
                       smBt + ck * 16 * KM_STRIDE + btFrag + (wn + np * 16) * 2);
            #pragma unroll
            for (int mi = 0; mi < 4; mi++)
                #pragma unroll
                for (int ni = 0; ni < 4; ni++)
                    mma_fp16(acc[mi][ni], afr[mi], bfr[ni]);
        }
        __syncthreads();
    }

    // ---- phase 2: inter-chunk, K = NS = 128, BK=32 ----
    const __half* crow = g_xc_h + ((size_t)b * LL + c * CS) * CONVD + DINNER + NS;
    const __half* prow = g_prev_h + (size_t)z * HP * NS;
    for (int k0 = 0; k0 < NS; k0 += 32) {
        const __half* cr = crow + (size_t)l_loc * CONVD + k0 + ac16;
        const __half* pr = prow + (size_t)arow * NS + k0 + ac16;
        #pragma unroll
        for (int q = 0; q < 2; q++) {
            uint4 cv = *(const uint4*)(cr + q * 8);
            __half2* cp = (__half2*)&cv;
            #pragma unroll
            for (int e = 0; e < 4; e++) cp[e] = __hmul2(cp[e], eAl2);
            *(uint4*)&As[arow][ac16 + q * 8] = cv;
            *(uint4*)&B2[arow][ac16 + q * 8] = *(const uint4*)(pr + q * 8);
        }
        __syncthreads();
        #pragma unroll
        for (int ck = 0; ck < 2; ck++) {
            uint32_t afr[4][4], bfr[4][2];
            #pragma unroll
            for (int mi = 0; mi < 4; mi++)
                ldsm4(afr[mi][0], afr[mi][1], afr[mi][2], afr[mi][3],
                      smA + aFrag + ck * 32 + mi * (16 * RM2_STRIDE));
            #pragma unroll
            for (int np = 0; np < 2; np++)
                ldsm4(bfr[2 * np][0], bfr[2 * np][1], bfr[2 * np + 1][0], bfr[2 * np + 1][1],
                      smB2 + b2Frag + ck * 32 + np * (16 * RM2_STRIDE));
            #pragma unroll
            for (int mi = 0; mi < 4; mi++)
                #pragma unroll
                for (int ni = 0; ni < 4; ni++)
                    mma_fp16(acc[mi][ni], afr[mi], bfr[ni]);
        }
        __syncthreads();
    }

    const float Dh = Dp[h];
    const int g = lane >> 2, tt = lane & 3;
    #pragma unroll
    for (int mi = 0; mi < 4; mi++)
        #pragma unroll
        for (int ni = 0; ni < 4; ni++) {
            int l0 = m0 + wm + mi * 16 + g;
            int p = wn + ni * 8 + 2 * tt;
            float2 xv0 = __half22float2(*(const __half2*)(xrow + (size_t)l0 * CONVD + p));
            float2 xv1 = __half22float2(*(const __half2*)(xrow + (size_t)(l0 + 8) * CONVD + p));
            __half* o0 = g_y_h + ((size_t)b * LL + c * CS + l0) * DINNER + h * HP + p;
            __half* o1 = g_y_h + ((size_t)b * LL + c * CS + l0 + 8) * DINNER + h * HP + p;
            *(__half2*)o0 = __floats2half2_rn(acc[mi][ni][0] + Dh * xv0.x,
                                              acc[mi][ni][1] + Dh * xv0.y);
            *(__half2*)o1 = __floats2half2_rn(acc[mi][ni][2] + Dh * xv1.x,
                                              acc[mi][ni][3] + Dh * xv1.y);
        }
}

// ---------------- gating (silu(z)) + RMS norm -> fp16 ----------------
__global__ void gate_norm(const float* __restrict__ norm_w)
{
    const int row = blockIdx.x;
    const int t = threadIdx.x;
    __shared__ float red[256];
    float vals[8];
    float local = 0.f;
    const __half* yrow = g_y_h + (size_t)row * DINNER;
    const __half* zrow = g_zx_h + (size_t)row * DIP;
    #pragma unroll
    for (int e = 0; e < 8; e++) {
        int i = e * 256 + t;
        float zv = __half2float(zrow[i]);
        float gv = __half2float(yrow[i]) * zv / (1.f + __expf(-zv));
        vals[e] = gv;
        local += gv * gv;
    }
    red[t] = local;
    __syncthreads();
    for (int off = 128; off > 0; off >>= 1) {
        if (t < off) red[t] += red[t + off];
        __syncthreads();
    }
    float scale = rsqrtf(red[0] / (float)DINNER + 1e-5f);
    __half* out = g_yg_h + (size_t)row * DINNER;
    #pragma unroll
    for (int e = 0; e < 8; e++) {
        int i = e * 256 + t;
        out[i] = __float2half(vals[e] * scale * norm_w[i]);
    }
}

// ---------------- host launcher ----------------
extern "C" void kernel_launch(void* const* d_in, const int* in_sizes, int n_in,
                              void* d_out, int out_size)
{
    const float* u       = (const float*)d_in[0];
    const float* W_in    = (const float*)d_in[1];
    const float* conv_w  = (const float*)d_in[2];
    const float* conv_b  = (const float*)d_in[3];
    const float* dt_bias = (const float*)d_in[4];
    const float* A_log   = (const float*)d_in[5];
    const float* Dp      = (const float*)d_in[6];
    const float* norm_w  = (const float*)d_in[7];
    const float* W_out   = (const float*)d_in[8];
    float* out = (float*)d_out;

    float* cbt;
    __half *zxh, *uh, *wih, *woh, *xch, *ygh;
    cudaGetSymbolAddress((void**)&cbt, g_CBT);
    cudaGetSymbolAddress((void**)&zxh, g_zx_h);
    cudaGetSymbolAddress((void**)&uh,  g_u_h);
    cudaGetSymbolAddress((void**)&wih, g_Win_h);
    cudaGetSymbolAddress((void**)&woh, g_Wout_h);
    cudaGetSymbolAddress((void**)&xch, g_xc_h);
    cudaGetSymbolAddress((void**)&ygh, g_yg_h);

    const int gemmSmem = GSTG * (A_STG_B + B_STG_B);  // 92160 B
    cudaFuncSetAttribute(gemm_fp16_nt,
                         cudaFuncAttributeMaxDynamicSharedMemorySize, gemmSmem);

    // 0) convert dense-GEMM inputs to fp16
    {
        int nu = BB * LL * DM;
        round_fp16<<<(nu / 4 + 255) / 256, 256>>>(u, uh, nu);
        int nwi = DIP * DM;
        round_fp16<<<(nwi / 4 + 255) / 256, 256>>>(W_in, wih, nwi);
        int nwo = DM * DINNER;
        round_fp16<<<(nwo / 4 + 255) / 256, 256>>>(W_out, woh, nwo);
    }

    // 1) in-proj (fp16 MMA, fp16 output)
    gemm_fp16_nt<<<dim3((DIP + 127) / 128, (BB * LL) / 256, 1), 256, gemmSmem>>>(
        uh, DM, 0, wih, DM, 0, zxh, DIP, 0, DIP, DM, 1);

    // 2) conv + silu + dt softplus (fp16 in/out)
    conv_silu_dt<<<dim3(CONVD / 256, BB * LL), 256>>>(conv_w, conv_b, dt_bias);

    // 3) per-chunk cumsum of dA
    chunk_cumsum<<<BB * NH * NC, CS>>>(A_log);

    // 4) CBT[b,c] = C @ B^T (fp16 MMA, fp32 output)
    gemm_fp16_nt<<<dim3(2, 1, BB * NC), 256, gemmSmem>>>(
        xch + DINNER + NS, CONVD, (long long)CS * CONVD,
        xch + DINNER,      CONVD, (long long)CS * CONVD,
        cbt, CS, (long long)CS * CS,
        CS, NS, 0);

    // 5) per-chunk states (fp16 MMA, BK=32)
    states_fp16<<<BB * NC * NH, 256>>>();

    // 6) inter-chunk scan (half2)
    chunk_scan<<<dim3(BB * NH, (HP * NS) / 512), 256>>>();

    // 7) Y = diag + off + D*x (fp16 MMA, BK=32, fp16 output)
    y_fp16<<<dim3(2, BB * NC * NH), 256>>>(Dp);

    // 8) gating + RMS norm (fp16 in/out)
    gate_norm<<<BB * LL, 256>>>(norm_w);

    // 9) out-proj (fp16 MMA, fp32 output)
    gemm_fp16_nt<<<dim3(DM / 128, (BB * LL) / 256, 1), 256, gemmSmem>>>(
        ygh, DINNER, 0, woh, DINNER, 0, out, DM, 0, DM, DINNER, 0);
}

// round 17
// speedup vs baseline: 1.0507x; 1.0507x over previous
#include <cuda_runtime.h>
#include <cuda_fp16.h>
#include <math.h>
#include <stdint.h>

// ---------------- problem constants ----------------
#define BB 4
#define LL 2048
#define DM 1024
#define DIP 4368          // 2*D_INNER + 2*D_STATE + NHEADS
#define DINNER 2048
#define CONVD 2304        // D_INNER + 2*D_STATE
#define NH 16
#define HP 128            // head dim
#define NS 128            // state dim
#define CS 256            // chunk size
#define NC 8              // chunks per sequence

// ---------------- scratch (device globals; no allocation) ----------------
__device__ __half g_zx_h[(size_t)BB * LL * DIP];      // in-proj output (fp16)
__device__ __half g_xc_h[(size_t)BB * LL * CONVD];    // conv+silu output (fp16)
__device__ float g_dt[(size_t)BB * LL * NH];          // softplus(dt)
__device__ float g_Acs[(size_t)BB * NH * NC * CS];    // per-chunk inclusive cumsum of dA
__device__ float g_CBT[(size_t)BB * NC * CS * CS];    // C @ B^T per (b,chunk)
__device__ __half g_states_h[(size_t)BB * NC * NH * HP * NS];
__device__ __half g_prev_h[(size_t)BB * NC * NH * HP * NS];
__device__ __half g_y_h[(size_t)BB * LL * DINNER];    // pre-out-proj activations (fp16)
__device__ __half g_u_h[(size_t)BB * LL * DM];        // fp16 u
__device__ __half g_Win_h[(size_t)DIP * DM];          // fp16 W_in
__device__ __half g_Wout_h[(size_t)DM * DINNER];      // fp16 W_out
__device__ __half g_yg_h[(size_t)BB * LL * DINNER];   // fp16 gated+normed y

// ---------------- helpers ----------------
__device__ __forceinline__ void mma_fp16(float c[4], const uint32_t a[4], const uint32_t b[2]) {
    asm volatile(
        "mma.sync.aligned.m16n8k16.row.col.f32.f16.f16.f32 "
        "{%0,%1,%2,%3}, {%4,%5,%6,%7}, {%8,%9}, {%0,%1,%2,%3};"
        : "+f"(c[0]), "+f"(c[1]), "+f"(c[2]), "+f"(c[3])
        : "r"(a[0]), "r"(a[1]), "r"(a[2]), "r"(a[3]), "r"(b[0]), "r"(b[1]));
}

__device__ __forceinline__ void ldsm4(uint32_t& r0, uint32_t& r1, uint32_t& r2, uint32_t& r3,
                                      uint32_t addr) {
    asm volatile("ldmatrix.sync.aligned.m8n8.x4.shared.b16 {%0,%1,%2,%3}, [%4];"
                 : "=r"(r0), "=r"(r1), "=r"(r2), "=r"(r3) : "r"(addr));
}

__device__ __forceinline__ void ldsm4t(uint32_t& r0, uint32_t& r1, uint32_t& r2, uint32_t& r3,
                                       uint32_t addr) {
    asm volatile("ldmatrix.sync.aligned.m8n8.x4.trans.shared.b16 {%0,%1,%2,%3}, [%4];"
                 : "=r"(r0), "=r"(r1), "=r"(r2), "=r"(r3) : "r"(addr));
}

__device__ __forceinline__ void cp16(uint32_t dst, const void* src, bool ok) {
    int sz = ok ? 16 : 0;
    asm volatile("cp.async.ca.shared.global [%0], [%1], 16, %2;\n"
                 :: "r"(dst), "l"(src), "r"(sz));
}
#define CP_COMMIT() asm volatile("cp.async.commit_group;\n")
#define CP_WAIT1()  asm volatile("cp.async.wait_group 1;\n" ::: "memory")

// ---------------- elementwise fp32 -> fp16 ----------------
__global__ void round_fp16(const float* __restrict__ s, __half* __restrict__ d, int n)
{
    int i = (blockIdx.x * 256 + threadIdx.x) * 4;
    if (i >= n) return;
    float4 v = *(const float4*)(s + i);
    *(__half2*)(d + i)     = __floats2half2_rn(v.x, v.y);
    *(__half2*)(d + i + 2) = __floats2half2_rn(v.z, v.w);
}

// ---------------- fp16 NT GEMM: 256 threads, 8 warps, 256x128 CTA tile ----------------
#define GSTG 3
#define A_STG_B (256 * 80)
#define B_STG_B (128 * 80)
#define GB_OFF (GSTG * A_STG_B)
__global__ __launch_bounds__(256, 1) void gemm_fp16_nt(
    const __half* __restrict__ A, int lda, long long sA,
    const __half* __restrict__ B, int ldb, long long sB,
    void* __restrict__ C, int ldc, long long sC,
    int N, int K, int outHalf)
{
    extern __shared__ char smraw[];
    const __half* Ab = A + (size_t)blockIdx.z * sA;
    const __half* Bb = B + (size_t)blockIdx.z * sB;
    const int m0 = blockIdx.y * 256, n0 = blockIdx.x * 128;
    const int t = threadIdx.x;
    const int lane = t & 31, w = t >> 5;
    const int wm = (w >> 1) * 64, wn = (w & 1) * 64;

    const bool bldr = (t < 128);
    const bool bok = bldr && ((n0 + t) < N);
    const __half* aS = Ab + (size_t)(m0 + t) * lda;
    const __half* bS = Bb + (size_t)(bok ? n0 + t : 0) * ldb;
    const uint32_t smBase = (uint32_t)__cvta_generic_to_shared(smraw);
    const uint32_t dA = smBase + t * 80;
    const uint32_t dB = smBase + GB_OFF + t * 80;

    const uint32_t aFragOff = (uint32_t)((wm + (lane & 15)) * 80 + (lane >> 4) * 16);
    const uint32_t bFragOff = (uint32_t)((wn + ((lane >> 4) << 3) + (lane & 7)) * 80
                                         + ((lane >> 3) & 1) * 16);

    float acc[4][8][4];
    #pragma unroll
    for (int i = 0; i < 4; i++)
        #pragma unroll
        for (int j = 0; j < 8; j++)
            #pragma unroll
            for (int q = 0; q < 4; q++) acc[i][j][q] = 0.f;

    const int nIter = K >> 5;
    #pragma unroll
    for (int s = 0; s < GSTG - 1; s++) {
        const uint32_t offA = s * A_STG_B;
        const uint32_t offB = s * B_STG_B;
        const int k0 = s << 5;
        cp16(dA + offA,      aS + k0,      true);
        cp16(dA + offA + 16, aS + k0 + 8,  true);
        cp16(dA + offA + 32, aS + k0 + 16, true);
        cp16(dA + offA + 48, aS + k0 + 24, true);
        if (bldr) {
            cp16(dB + offB,      bS + k0,      bok);
            cp16(dB + offB + 16, bS + k0 + 8,  bok);
            cp16(dB + offB + 32, bS + k0 + 16, bok);
            cp16(dB + offB + 48, bS + k0 + 24, bok);
        }
        CP_COMMIT();
    }

    for (int it = 0; it < nIter; it++) {
        CP_WAIT1();
        __syncthreads();
        const int pf = it + GSTG - 1;
        if (pf < nIter) {
            const uint32_t offA = (pf % GSTG) * A_STG_B;
            const uint32_t offB = (pf % GSTG) * B_STG_B;
            const int k0 = pf << 5;
            cp16(dA + offA,      aS + k0,      true);
            cp16(dA + offA + 16, aS + k0 + 8,  true);
            cp16(dA + offA + 32, aS + k0 + 16, true);
            cp16(dA + offA + 48, aS + k0 + 24, true);
            if (bldr) {
                cp16(dB + offB,      bS + k0,      bok);
                cp16(dB + offB + 16, bS + k0 + 8,  bok);
                cp16(dB + offB + 32, bS + k0 + 16, bok);
                cp16(dB + offB + 48, bS + k0 + 24, bok);
            }
        }
        CP_COMMIT();

        const uint32_t aOct = smBase + (it % GSTG) * A_STG_B + aFragOff;
        const uint32_t bOct = smBase + GB_OFF + (it % GSTG) * B_STG_B + bFragOff;
        uint32_t afr[2][4][4], bfr[2][8][2];
        #pragma unroll
        for (int ck = 0; ck < 2; ck++) {
            #pragma unroll
            for (int mi = 0; mi < 4; mi++)
                ldsm4(afr[ck][mi][0], afr[ck][mi][1], afr[ck][mi][2], afr[ck][mi][3],
                      aOct + ck * 32 + mi * (16 * 80));
            #pragma unroll
            for (int j = 0; j < 4; j++)
                ldsm4(bfr[ck][2 * j][0], bfr[ck][2 * j][1],
                      bfr[ck][2 * j + 1][0], bfr[ck][2 * j + 1][1],
                      bOct + ck * 32 + j * (16 * 80));
        }
        #pragma unroll
        for (int ck = 0; ck < 2; ck++)
            #pragma unroll
            for (int mi = 0; mi < 4; mi++)
                #pragma unroll
                for (int ni = 0; ni < 8; ni++)
                    mma_fp16(acc[mi][ni], afr[ck][mi], bfr[ck][ni]);
    }

    const int g = lane >> 2, tt = lane & 3;
    if (outHalf) {
        __half* Cb = (__half*)C + (size_t)blockIdx.z * sC;
        #pragma unroll
        for (int mi = 0; mi < 4; mi++)
            #pragma unroll
            for (int ni = 0; ni < 8; ni++) {
                int row = m0 + wm + mi * 16 + g;
                int col = n0 + wn + ni * 8 + 2 * tt;
                if (col < N) {
                    *(__half2*)(Cb + (size_t)row * ldc + col) =
                        __floats2half2_rn(acc[mi][ni][0], acc[mi][ni][1]);
                    *(__half2*)(Cb + (size_t)(row + 8) * ldc + col) =
                        __floats2half2_rn(acc[mi][ni][2], acc[mi][ni][3]);
                }
            }
    } else {
        float* Cb = (float*)C + (size_t)blockIdx.z * sC;
        #pragma unroll
        for (int mi = 0; mi < 4; mi++)
            #pragma unroll
            for (int ni = 0; ni < 8; ni++) {
                int row = m0 + wm + mi * 16 + g;
                int col = n0 + wn + ni * 8 + 2 * tt;
                if (col < N) {
                    *(float2*)(Cb + (size_t)row * ldc + col) =
                        make_float2(acc[mi][ni][0], acc[mi][ni][1]);
                    *(float2*)(Cb + (size_t)(row + 8) * ldc + col) =
                        make_float2(acc[mi][ni][2], acc[mi][ni][3]);
                }
            }
    }
}

// ---------------- tiled depthwise conv (K=4) + SiLU + dt softplus ----------------
// Block: 256-channel slice x 64 output rows; smem tile with 3-row halo.
#define CROWS 64
__global__ __launch_bounds__(256) void conv_silu_dt(const float* __restrict__ conv_w,
                                                    const float* __restrict__ conv_b,
                                                    const float* __restrict__ dt_bias)
{
    __shared__ __half sx[CROWS + 3][256];
    const int bx = blockIdx.x;            // channel tile (0..CONVD/256-1)
    const int r0 = blockIdx.y * CROWS;    // first output row (64-aligned; LL%64==0)
    const int t = threadIdx.x;
    const int seq = r0 >> 11;             // sequence index (LL = 2048)

    // load (CROWS+3) x 256 halves; halo rows crossing sequence boundary -> 0
    for (int i = t; i < (CROWS + 3) * 32; i += 256) {
        int r = i >> 5, ck = i & 31;
        int gr = r0 + r - 3;
        uint4 v = make_uint4(0, 0, 0, 0);
        if (gr >= 0 && (gr >> 11) == seq)
            v = *(const uint4*)(g_zx_h + (size_t)gr * DIP + DINNER + bx * 256 + ck * 8);
        *(uint4*)&sx[r][ck * 8] = v;
    }
    __syncthreads();

    // compute: thread -> channel pair (t & 127), row half (t >> 7)
    const int c2 = (t & 127) * 2;
    const int rbeg = (t >> 7) * (CROWS / 2);
    const int c = bx * 256 + c2;
    const float b0 = conv_b[c], b1 = conv_b[c + 1];
    float w0[4], w1[4];
    #pragma unroll
    for (int k = 0; k < 4; k++) {
        w0[k] = conv_w[c * 4 + k];
        w1[k] = conv_w[(c + 1) * 4 + k];
    }
    for (int r = rbeg; r < rbeg + CROWS / 2; r++) {
        float a0 = b0, a1 = b1;
        #pragma unroll
        for (int k = 0; k < 4; k++) {
            float2 xv = __half22float2(*(const __half2*)&sx[r + k][c2]);
            a0 += xv.x * w0[k];
            a1 += xv.y * w1[k];
        }
        a0 = a0 / (1.f + __expf(-a0));
        a1 = a1 / (1.f + __expf(-a1));
        *(__half2*)(g_xc_h + (size_t)(r0 + r) * CONVD + c) = __floats2half2_rn(a0, a1);
    }

    // dt softplus (only channel-block 0 does it): 64 rows x NH heads
    if (bx == 0) {
        for (int i = t; i < CROWS * NH; i += 256) {
            int r = i >> 4, hh = i & 15;
            float x = __half2float(g_zx_h[(size_t)(r0 + r) * DIP + DINNER + CONVD + hh])
                      + dt_bias[hh];
            float sp = (x > 20.f) ? x : log1pf(__expf(x));
            g_dt[(size_t)(r0 + r) * NH + hh] = sp;
        }
    }
}

// ---------------- per-chunk inclusive cumsum of dA = dt * A ----------------
__global__ void chunk_cumsum(const float* __restrict__ A_log)
{
    const int idx = blockIdx.x;
    const int c = idx % NC;
    const int h = (idx / NC) % NH;
    const int b = idx / (NC * NH);
    const int s = threadIdx.x;
    __shared__ float sh[CS];
    float Ah = -__expf(A_log[h]);
    sh[s] = g_dt[((size_t)b * LL + c * CS + s) * NH + h] * Ah;
    __syncthreads();
    for (int off = 1; off < CS; off <<= 1) {
        float u = (s >= off) ? sh[s - off] : 0.f;
        __syncthreads();
        sh[s] += u;
        __syncthreads();
    }
    g_Acs[(size_t)idx * CS + s] = sh[s];
}

// ---------------- states (fp16 MMA, 256 threads, BK=32, trans ldmatrix) ----------------
#define KM_STRIDE 272   // bytes per k-row (128 halves + 8 pad)
__global__ __launch_bounds__(256, 2) void states_fp16()
{
    const int z = blockIdx.x;
    const int h = z % NH;
    const int bc = z / NH;
    const int c = bc % NC;
    const int b = bc / NC;
    __shared__ __half Xs[32][136];
    __shared__ __half Bs[32][136];
    __shared__ float ws[CS];
    const int t = threadIdx.x;
    {
        const float* acs = g_Acs + ((size_t)(b * NH + h) * NC + c) * CS;
        float last = acs[CS - 1];
        float dtv = g_dt[((size_t)b * LL + c * CS + t) * NH + h];
        ws[t] = dtv * __expf(last - acs[t]);
    }
    __syncthreads();
    const int lane = t & 31, w = t >> 5;
    const int wm = (w & 1) * 64, wn = (w >> 1) * 32;
    const int lr = t >> 3, lc = (t & 7) * 16;
    const uint32_t smX = (uint32_t)__cvta_generic_to_shared(&Xs[0][0]);
    const uint32_t smB = (uint32_t)__cvta_generic_to_shared(&Bs[0][0]);
    const uint32_t aRowOff = (uint32_t)(((lane & 7) + ((lane >> 4) << 3)) * KM_STRIDE
                                        + ((lane >> 3) & 1) * 16);
    const uint32_t bRowOff = (uint32_t)(((lane & 7) + ((lane >> 3) & 1) * 8) * KM_STRIDE
                                        + ((lane >> 4) << 4));

    float acc[4][4][4];
    #pragma unroll
    for (int i = 0; i < 4; i++)
        #pragma unroll
        for (int j = 0; j < 4; j++)
            #pragma unroll
            for (int q = 0; q < 4; q++) acc[i][j][q] = 0.f;

    const __half* xbase = g_xc_h + ((size_t)b * LL + c * CS) * CONVD + h * HP;
    const __half* bbase = g_xc_h + ((size_t)b * LL + c * CS) * CONVD + DINNER;

    for (int k0 = 0; k0 < CS; k0 += 32) {
        const __half2 wsv2 = __float2half2_rn(ws[k0 + lr]);
        const __half* xr = xbase + (size_t)(k0 + lr) * CONVD + lc;
        const __half* br = bbase + (size_t)(k0 + lr) * CONVD + lc;
        #pragma unroll
        for (int q = 0; q < 2; q++) {
            uint4 xv = *(const uint4*)(xr + q * 8);
            __half2* xp = (__half2*)&xv;
            #pragma unroll
            for (int e = 0; e < 4; e++) xp[e] = __hmul2(xp[e], wsv2);
            *(uint4*)&Xs[lr][lc + q * 8] = xv;
            *(uint4*)&Bs[lr][lc + q * 8] = *(const uint4*)(br + q * 8);
        }
        __syncthreads();
        #pragma unroll
        for (int ck = 0; ck < 2; ck++) {
            uint32_t afr[4][4], bfr[4][2];
            const uint32_t cOff = ck * 16 * KM_STRIDE;
            #pragma unroll
            for (int mi = 0; mi < 4; mi++)
                ldsm4t(afr[mi][0], afr[mi][1], afr[mi][2], afr[mi][3],
                       smX + cOff + aRowOff + (wm + mi * 16) * 2);
            #pragma unroll
            for (int np = 0; np < 2; np++)
                ldsm4t(bfr[2 * np][0], bfr[2 * np][1], bfr[2 * np + 1][0], bfr[2 * np + 1][1],
                       smB + cOff + bRowOff + (wn + np * 16) * 2);
            #pragma unroll
            for (int mi = 0; mi < 4; mi++)
                #pragma unroll
                for (int ni = 0; ni < 4; ni++)
                    mma_fp16(acc[mi][ni], afr[mi], bfr[ni]);
        }
        __syncthreads();
    }

    __half* sout = g_states_h + (size_t)z * HP * NS;
    const int g = lane >> 2, tt = lane & 3;
    #pragma unroll
    for (int mi = 0; mi < 4; mi++)
        #pragma unroll
        for (int ni = 0; ni < 4; ni++) {
            int row = wm + mi * 16 + g;
            int col = wn + ni * 8 + 2 * tt;
            *(__half2*)(sout + (size_t)row * NS + col) =
                __floats2half2_rn(acc[mi][ni][0], acc[mi][ni][1]);
            *(__half2*)(sout + (size_t)(row + 8) * NS + col) =
                __floats2half2_rn(acc[mi][ni][2], acc[mi][ni][3]);
        }
}

// ---------------- sequential scan over chunks (half2, element-parallel) ----------------
__global__ void chunk_scan()
{
    const int bh = blockIdx.x;
    const int b = bh / NH, h = bh % NH;
    __shared__ float dec[NC];
    if (threadIdx.x < NC)
        dec[threadIdx.x] = __expf(g_Acs[((size_t)(b * NH + h) * NC + threadIdx.x) * CS + CS - 1]);
    __syncthreads();
    const int idx = (blockIdx.y * 256 + threadIdx.x) * 2;
    float2 carry = make_float2(0.f, 0.f);
    #pragma unroll
    for (int c = 0; c < NC; c++) {
        size_t base = ((size_t)((b * NC + c) * NH + h)) * HP * NS + idx;
        *(__half2*)(g_prev_h + base) = __floats2half2_rn(carry.x, carry.y);
        float2 s = __half22float2(*(const __half2*)(g_states_h + base));
        carry.x = carry.x * dec[c] + s.x;
        carry.y = carry.y * dec[c] + s.y;
    }
}

// ---------------- Y (fp16 MMA, 256 threads, BK=32) ----------------
#define RM2_STRIDE 80   // bytes per row (32 halves + 8 pad)
__global__ __launch_bounds__(256, 2) void y_fp16(const float* __restrict__ Dp)
{
    const int z = blockIdx.y;
    const int h = z % NH;
    const int bc = z / NH;
    const int c = bc % NC;
    const int b = bc / NC;
    const int m0 = blockIdx.x * 128;

    __shared__ float sAcs[CS], sdt[CS];
    __shared__ float sh_e[32];
    __shared__ __half As[128][40];
    __shared__ __half Bt[32][136];
    __shared__ __half B2[128][40];
    const int t = threadIdx.x;
    {
        const float* acs = g_Acs + ((size_t)(b * NH + h) * NC + c) * CS;
        sAcs[t] = acs[t];
        sdt[t] = g_dt[((size_t)b * LL + c * CS + t) * NH + h];
    }
    __syncthreads();

    const int lane = t & 31, w = t >> 5;
    const int wm = (w & 1) * 64, wn = (w >> 1) * 32;
    const int arow = t >> 1, ac16 = (t & 1) * 16;
    const int l_loc = m0 + arow;
    const float acs_l = sAcs[l_loc];
    const __half2 eAl2 = __float2half2_rn(__expf(acs_l));
    const int xr32 = t >> 3, xc16 = (t & 7) * 16;

    const uint32_t smA  = (uint32_t)__cvta_generic_to_shared(&As[0][0]);
    const uint32_t smBt = (uint32_t)__cvta_generic_to_shared(&Bt[0][0]);
    const uint32_t smB2 = (uint32_t)__cvta_generic_to_shared(&B2[0][0]);
    const uint32_t aFrag  = (uint32_t)((wm + (lane & 15)) * RM2_STRIDE + (lane >> 4) * 16);
    const uint32_t btFrag = (uint32_t)(((lane & 7) + ((lane >> 3) & 1) * 8) * KM_STRIDE
                                       + ((lane >> 4) << 4));
    const uint32_t b2Frag = (uint32_t)((wn + ((lane >> 4) << 3) + (lane & 7)) * RM2_STRIDE
                                       + ((lane >> 3) & 1) * 16);

    float acc[4][4][4];
    #pragma unroll
    for (int i = 0; i < 4; i++)
        #pragma unroll
        for (int j = 0; j < 4; j++)
            #pragma unroll
            for (int q = 0; q < 4; q++) acc[i][j][q] = 0.f;

    const float* cbt_l = g_CBT + (size_t)bc * CS * CS + (size_t)l_loc * CS;
    const __half* xrow = g_xc_h + ((size_t)b * LL + c * CS) * CONVD + h * HP;

    // ---- phase 1: intra-chunk, K = m0+128, BK=32 (factorized decay exp) ----
    const int K1 = m0 + 128;
    for (int k0 = 0; k0 < K1; k0 += 32) {
        if (t < 32)
            sh_e[t] = __expf(sAcs[k0 + 31] - sAcs[k0 + t]) * sdt[k0 + t];
        __syncthreads();
        const float e_row = (l_loc >= k0) ? __expf(acs_l - sAcs[k0 + 31]) : 0.f;
        #pragma unroll
        for (int j = 0; j < 16; j += 2) {
            int s = k0 + ac16 + j;
            float v0 = (s     <= l_loc) ? cbt_l[s]     * e_row * sh_e[ac16 + j]     : 0.f;
            float v1 = (s + 1 <= l_loc) ? cbt_l[s + 1] * e_row * sh_e[ac16 + j + 1] : 0.f;
            *(__half2*)&As[arow][ac16 + j] = __floats2half2_rn(v0, v1);
        }
        const __half* xr = xrow + (size_t)(k0 + xr32) * CONVD + xc16;
        *(uint4*)&Bt[xr32][xc16]     = *(const uint4*)(xr);
        *(uint4*)&Bt[xr32][xc16 + 8] = *(const uint4*)(xr + 8);
        __syncthreads();
        #pragma unroll
        for (int ck = 0; ck < 2; ck++) {
            uint32_t afr[4][4], bfr[4][2];
            #pragma unroll
            for (int mi = 0; mi < 4; mi++)
                ldsm4(afr[mi][0], afr[mi][1], afr[mi][2], afr[mi][3],
                      smA + aFrag + ck * 32 + mi * (16 * RM2_STRIDE));
            #pragma unroll
            for (int np = 0; np < 2; np++)
                ldsm4t(bfr[2 * np][0], bfr[2 * np][1], bfr[2 * np + 1][0], bfr[2 * np + 1][1],
                       smBt + ck * 16 * KM_STRIDE + btFrag + (wn + np * 16) * 2);
            #pragma unroll
            for (int mi = 0; mi < 4; mi++)
                #pragma unroll
                for (int ni = 0; ni < 4; ni++)
                    mma_fp16(acc[mi][ni], afr[mi], bfr[ni]);
        }
        __syncthreads();
    }

    // ---- phase 2: inter-chunk, K = NS = 128, BK=32 ----
    const __half* crow = g_xc_h + ((size_t)b * LL + c * CS) * CONVD + DINNER + NS;
    const __half* prow = g_prev_h + (size_t)z * HP * NS;
    for (int k0 = 0; k0 < NS; k0 += 32) {
        const __half* cr = crow + (size_t)l_loc * CONVD + k0 + ac16;
        const __half* pr = prow + (size_t)arow * NS + k0 + ac16;
        #pragma unroll
        for (int q = 0; q < 2; q++) {
            uint4 cv = *(const uint4*)(cr + q * 8);
            __half2* cp = (__half2*)&cv;
            #pragma unroll
            for (int e = 0; e < 4; e++) cp[e] = __hmul2(cp[e], eAl2);
            *(uint4*)&As[arow][ac16 + q * 8] = cv;
            *(uint4*)&B2[arow][ac16 + q * 8] = *(const uint4*)(pr + q * 8);
        }
        __syncthreads();
        #pragma unroll
        for (int ck = 0; ck < 2; ck++) {
            uint32_t afr[4][4], bfr[4][2];
            #pragma unroll
            for (int mi = 0; mi < 4; mi++)
                ldsm4(afr[mi][0], afr[mi][1], afr[mi][2], afr[mi][3],
                      smA + aFrag + ck * 32 + mi * (16 * RM2_STRIDE));
            #pragma unroll
            for (int np = 0; np < 2; np++)
                ldsm4(bfr[2 * np][0], bfr[2 * np][1], bfr[2 * np + 1][0], bfr[2 * np + 1][1],
                      smB2 + b2Frag + ck * 32 + np * (16 * RM2_STRIDE));
            #pragma unroll
            for (int mi = 0; mi < 4; mi++)
                #pragma unroll
                for (int ni = 0; ni < 4; ni++)
                    mma_fp16(acc[mi][ni], afr[mi], bfr[ni]);
        }
        __syncthreads();
    }

    const float Dh = Dp[h];
    const int g = lane >> 2, tt = lane & 3;
    #pragma unroll
    for (int mi = 0; mi < 4; mi++)
        #pragma unroll
        for (int ni = 0; ni < 4; ni++) {
            int l0 = m0 + wm + mi * 16 + g;
            int p = wn + ni * 8 + 2 * tt;
            float2 xv0 = __half22float2(*(const __half2*)(xrow + (size_t)l0 * CONVD + p));
            float2 xv1 = __half22float2(*(const __half2*)(xrow + (size_t)(l0 + 8) * CONVD + p));
            __half* o0 = g_y_h + ((size_t)b * LL + c * CS + l0) * DINNER + h * HP + p;
            __half* o1 = g_y_h + ((size_t)b * LL + c * CS + l0 + 8) * DINNER + h * HP + p;
            *(__half2*)o0 = __floats2half2_rn(acc[mi][ni][0] + Dh * xv0.x,
                                              acc[mi][ni][1] + Dh * xv0.y);
            *(__half2*)o1 = __floats2half2_rn(acc[mi][ni][2] + Dh * xv1.x,
                                              acc[mi][ni][3] + Dh * xv1.y);
        }
}

// ---------------- gating (silu(z)) + RMS norm -> fp16 ----------------
__global__ void gate_norm(const float* __restrict__ norm_w)
{
    const int row = blockIdx.x;
    const int t = threadIdx.x;
    __shared__ float red[256];
    float vals[8];
    float local = 0.f;
    const __half* yrow = g_y_h + (size_t)row * DINNER;
    const __half* zrow = g_zx_h + (size_t)row * DIP;
    #pragma unroll
    for (int e = 0; e < 8; e++) {
        int i = e * 256 + t;
        float zv = __half2float(zrow[i]);
        float gv = __half2float(yrow[i]) * zv / (1.f + __expf(-zv));
        vals[e] = gv;
        local += gv * gv;
    }
    red[t] = local;
    __syncthreads();
    for (int off = 128; off > 0; off >>= 1) {
        if (t < off) red[t] += red[t + off];
        __syncthreads();
    }
    float scale = rsqrtf(red[0] / (float)DINNER + 1e-5f);
    __half* out = g_yg_h + (size_t)row * DINNER;
    #pragma unroll
    for (int e = 0; e < 8; e++) {
        int i = e * 256 + t;
        out[i] = __float2half(vals[e] * scale * norm_w[i]);
    }
}

// ---------------- host launcher ----------------
extern "C" void kernel_launch(void* const* d_in, const int* in_sizes, int n_in,
                              void* d_out, int out_size)
{
    const float* u       = (const float*)d_in[0];
    const float* W_in    = (const float*)d_in[1];
    const float* conv_w  = (const float*)d_in[2];
    const float* conv_b  = (const float*)d_in[3];
    const float* dt_bias = (const float*)d_in[4];
    const float* A_log   = (const float*)d_in[5];
    const float* Dp      = (const float*)d_in[6];
    const float* norm_w  = (const float*)d_in[7];
    const float* W_out   = (const float*)d_in[8];
    float* out = (float*)d_out;

    float* cbt;
    __half *zxh, *uh, *wih, *woh, *xch, *ygh;
    cudaGetSymbolAddress((void**)&cbt, g_CBT);
    cudaGetSymbolAddress((void**)&zxh, g_zx_h);
    cudaGetSymbolAddress((void**)&uh,  g_u_h);
    cudaGetSymbolAddress((void**)&wih, g_Win_h);
    cudaGetSymbolAddress((void**)&woh, g_Wout_h);
    cudaGetSymbolAddress((void**)&xch, g_xc_h);
    cudaGetSymbolAddress((void**)&ygh, g_yg_h);

    const int gemmSmem = GSTG * (A_STG_B + B_STG_B);  // 92160 B
    cudaFuncSetAttribute(gemm_fp16_nt,
                         cudaFuncAttributeMaxDynamicSharedMemorySize, gemmSmem);

    // 0) convert dense-GEMM inputs to fp16
    {
        int nu = BB * LL * DM;
        round_fp16<<<(nu / 4 + 255) / 256, 256>>>(u, uh, nu);
        int nwi = DIP * DM;
        round_fp16<<<(nwi / 4 + 255) / 256, 256>>>(W_in, wih, nwi);
        int nwo = DM * DINNER;
        round_fp16<<<(nwo / 4 + 255) / 256, 256>>>(W_out, woh, nwo);
    }

    // 1) in-proj (fp16 MMA, fp16 output)
    gemm_fp16_nt<<<dim3((DIP + 127) / 128, (BB * LL) / 256, 1), 256, gemmSmem>>>(
        uh, DM, 0, wih, DM, 0, zxh, DIP, 0, DIP, DM, 1);

    // 2) tiled conv + silu + dt softplus
    conv_silu_dt<<<dim3(CONVD / 256, (BB * LL) / CROWS), 256>>>(conv_w, conv_b, dt_bias);

    // 3) per-chunk cumsum of dA
    chunk_cumsum<<<BB * NH * NC, CS>>>(A_log);

    // 4) CBT[b,c] = C @ B^T (fp16 MMA, fp32 output)
    gemm_fp16_nt<<<dim3(2, 1, BB * NC), 256, gemmSmem>>>(
        xch + DINNER + NS, CONVD, (long long)CS * CONVD,
        xch + DINNER,      CONVD, (long long)CS * CONVD,
        cbt, CS, (long long)CS * CS,
        CS, NS, 0);

    // 5) per-chunk states (fp16 MMA, BK=32)
    states_fp16<<<BB * NC * NH, 256>>>();

    // 6) inter-chunk scan (half2)
    chunk_scan<<<dim3(BB * NH, (HP * NS) / 512), 256>>>();

    // 7) Y = diag + off + D*x (fp16 MMA, BK=32, fp16 output)
    y_fp16<<<dim3(2, BB * NC * NH), 256>>>(Dp);

    // 8) gating + RMS norm (fp16 in/out)
    gate_norm<<<BB * LL, 256>>>(norm_w);

    // 9) out-proj (fp16 MMA, fp32 output)
    gemm_fp16_nt<<<dim3(DM / 128, (BB * LL) / 256, 1), 256, gemmSmem>>>(
        ygh, DINNER, 0, woh, DINNER, 0, out, DM, 0, DM, DINNER, 0);
}